// round 6
// baseline (speedup 1.0000x reference)
#include <cuda_runtime.h>

#define NN   8192
#define FIN  128
#define FOUT 64
#define RT   64      // rows per CTA in attention kernel
#define JB   64      // j-chunk
#define ALPHA_LR 0.2f

// Scratch (device globals — no allocation allowed)
__device__ __align__(16) float g_h[NN * FOUT];
__device__ __align__(16) float g_s1[NN];
__device__ __align__(16) float g_s2[NN];

__device__ __forceinline__ unsigned long long pack2(float lo, float hi) {
    unsigned long long r;
    asm("mov.b64 %0, {%1, %2};" : "=l"(r) : "f"(lo), "f"(hi));
    return r;
}
__device__ __forceinline__ void unpack2(unsigned long long v, float& lo, float& hi) {
    asm("mov.b64 {%0, %1}, %2;" : "=f"(lo), "=f"(hi) : "l"(v));
}
// Packed fp32x2 FMA: d = a*b + d  (sm_100+; 2x FFMA throughput)
__device__ __forceinline__ void fma2(unsigned long long& d, unsigned long long a, unsigned long long b) {
    asm("fma.rn.f32x2 %0, %1, %2, %0;" : "+l"(d) : "l"(a), "l"(b));
}

// ---------------------------------------------------------------------------
// Kernel 1: h = x @ W ; s1 = h @ a1 ; s2 = h @ a2
// 128 CTAs x 256 thr; thread = (row, 16-col group)
// ---------------------------------------------------------------------------
__global__ __launch_bounds__(256) void gat_proj(const float* __restrict__ x,
                                                const float* __restrict__ W,
                                                const float* __restrict__ a) {
    __shared__ float W_s[FIN][FOUT];   // 32 KB
    const int t = threadIdx.x;
    {
        const float4* Wg = (const float4*)W;
        float4* Ws = (float4*)&W_s[0][0];
        #pragma unroll
        for (int i = 0; i < 8; i++) Ws[t + 256 * i] = Wg[t + 256 * i];
    }
    __syncthreads();

    const int row = blockIdx.x * 64 + (t >> 2);
    const int cb  = (t & 3) * 16;

    float acc[16];
    #pragma unroll
    for (int c = 0; c < 16; c++) acc[c] = 0.0f;

    const float4* xr = (const float4*)(x + (size_t)row * FIN);
    #pragma unroll 8
    for (int k4 = 0; k4 < 32; k4++) {
        const float4 xv = xr[k4];
        const int k = k4 * 4;
        #pragma unroll
        for (int c = 0; c < 16; c++) {
            acc[c] = fmaf(xv.x, W_s[k    ][cb + c], acc[c]);
            acc[c] = fmaf(xv.y, W_s[k + 1][cb + c], acc[c]);
            acc[c] = fmaf(xv.z, W_s[k + 2][cb + c], acc[c]);
            acc[c] = fmaf(xv.w, W_s[k + 3][cb + c], acc[c]);
        }
    }

    float4* hw = (float4*)(g_h + (size_t)row * FOUT + cb);
    #pragma unroll
    for (int q = 0; q < 4; q++)
        hw[q] = make_float4(acc[q*4], acc[q*4+1], acc[q*4+2], acc[q*4+3]);

    // attention logits: s1 = h.a1, s2 = h.a2  (a1 = a[0:64], a2 = a[64:128])
    float p1 = 0.0f, p2 = 0.0f;
    #pragma unroll
    for (int c = 0; c < 16; c++) {
        p1 = fmaf(acc[c], __ldg(&a[cb + c]),        p1);
        p2 = fmaf(acc[c], __ldg(&a[FOUT + cb + c]), p2);
    }
    // reduce across the 4 col-groups of this row (consecutive lanes)
    p1 += __shfl_xor_sync(0xffffffffu, p1, 1);
    p1 += __shfl_xor_sync(0xffffffffu, p1, 2);
    p2 += __shfl_xor_sync(0xffffffffu, p2, 1);
    p2 += __shfl_xor_sync(0xffffffffu, p2, 2);
    if ((t & 3) == 0) { g_s1[row] = p1; g_s2[row] = p2; }
}

// ---------------------------------------------------------------------------
// Kernel 2: masked softmax-attention, flash-style (unnormalized), f32x2 FMA.
// 128 CTAs (64 rows each) x 256 thr.
// Per chunk of 64 j's:
//   phase1: compute w = adj ? exp(lrelu(s1_i + s2_j)) : 0, store (w,w) pairs
//   phase2: 4x4 microtile rank-1 updates with fma.rn.f32x2
// adj/h/s2 for chunk n+1 are prefetched into registers during chunk n.
// ---------------------------------------------------------------------------
__global__ __launch_bounds__(256, 1) void gat_attn(const int* __restrict__ adj,
                                                   float* __restrict__ out) {
    __shared__ __align__(16) unsigned long long w2_s[JB][RT];  // 32 KB: (w,w) pairs, [j][row]
    __shared__ __align__(16) float h_s[JB][FOUT];              // 16 KB: [j][col]

    const int t = threadIdx.x;
    const int rbase = blockIdx.x * RT;

    // phase-1 identity: 4 threads per row, 16 j's each
    const int p1_row = t & 63;
    const int p1_js  = t >> 6;              // 0..3
    const float s1r  = g_s1[rbase + p1_row];
    float den = 0.0f;
    const int*   adj_row = adj + (size_t)(rbase + p1_row) * NN + p1_js * 16;
    const float* s2b     = g_s2 + p1_js * 16;

    // phase-2 identity: 16x16 thread grid, 4 rows x 4 cols microtile
    const int rt4 = (t >> 4) * 4;
    const int ct4 = (t & 15) * 4;

    unsigned long long acc[4][2];
    #pragma unroll
    for (int i = 0; i < 4; i++) { acc[i][0] = 0ull; acc[i][1] = 0ull; }

    // prefetch registers for chunk 0
    int4   A0, A1, A2, A3;
    float4 S0, S1, S2, S3;
    float4 H0, H1, H2, H3;
    {
        const int4* ap = (const int4*)adj_row;
        A0 = ap[0]; A1 = ap[1]; A2 = ap[2]; A3 = ap[3];
        const float4* sp = (const float4*)s2b;
        S0 = sp[0]; S1 = sp[1]; S2 = sp[2]; S3 = sp[3];
        const float4* hp = (const float4*)g_h;
        H0 = hp[t]; H1 = hp[t + 256]; H2 = hp[t + 512]; H3 = hp[t + 768];
    }

    for (int jb = 0; jb < NN; jb += JB) {
        __syncthreads();   // previous phase-2 done reading smem

        // commit prefetched h chunk
        {
            float4* hs = (float4*)&h_s[0][0];
            hs[t] = H0; hs[t + 256] = H1; hs[t + 512] = H2; hs[t + 768] = H3;
        }

        // compute + store duplicated weights
        const int jl = p1_js * 16;
        #define WST(off, av, s2f) do {                          \
            float e = s1r + (s2f);                              \
            e = fmaxf(e, ALPHA_LR * e);       /* leaky relu */  \
            float w = ((av) > 0) ? __expf(e) : 0.0f;            \
            den += w;                                           \
            w2_s[jl + (off)][p1_row] = pack2(w, w);             \
        } while (0)
        WST(0,  A0.x, S0.x); WST(1,  A0.y, S0.y); WST(2,  A0.z, S0.z); WST(3,  A0.w, S0.w);
        WST(4,  A1.x, S1.x); WST(5,  A1.y, S1.y); WST(6,  A1.z, S1.z); WST(7,  A1.w, S1.w);
        WST(8,  A2.x, S2.x); WST(9,  A2.y, S2.y); WST(10, A2.z, S2.z); WST(11, A2.w, S2.w);
        WST(12, A3.x, S3.x); WST(13, A3.y, S3.y); WST(14, A3.z, S3.z); WST(15, A3.w, S3.w);
        #undef WST

        // prefetch next chunk (hides DRAM latency behind phase-2)
        const int jn = jb + JB;
        if (jn < NN) {
            const int4* ap = (const int4*)(adj_row + jn);
            A0 = ap[0]; A1 = ap[1]; A2 = ap[2]; A3 = ap[3];
            const float4* sp = (const float4*)(s2b + jn);
            S0 = sp[0]; S1 = sp[1]; S2 = sp[2]; S3 = sp[3];
            const float4* hp = (const float4*)(g_h + (size_t)jn * FOUT);
            H0 = hp[t]; H1 = hp[t + 256]; H2 = hp[t + 512]; H3 = hp[t + 768];
        }

        __syncthreads();   // smem tiles ready

        // rank-1 accumulation: per j, 3 LDS.128 + 8 FFMA2
        #pragma unroll 8
        for (int jj = 0; jj < JB; jj++) {
            const ulonglong2 wa = *(const ulonglong2*)&w2_s[jj][rt4];
            const ulonglong2 wb = *(const ulonglong2*)&w2_s[jj][rt4 + 2];
            const ulonglong2 hv = *(const ulonglong2*)&h_s[jj][ct4];
            fma2(acc[0][0], wa.x, hv.x); fma2(acc[0][1], wa.x, hv.y);
            fma2(acc[1][0], wa.y, hv.x); fma2(acc[1][1], wa.y, hv.y);
            fma2(acc[2][0], wb.x, hv.x); fma2(acc[2][1], wb.x, hv.y);
            fma2(acc[3][0], wb.y, hv.x); fma2(acc[3][1], wb.y, hv.y);
        }
    }

    __syncthreads();
    // row-sum (denominator) reduction, overlaying h_s (phase-2 done)
    float* den_s = (float*)&h_s[0][0];
    den_s[p1_js * 64 + p1_row] = den;
    __syncthreads();
    if (t < 64)
        den_s[256 + t] = den_s[t] + den_s[64 + t] + den_s[128 + t] + den_s[192 + t];
    __syncthreads();

    // normalize + ELU + store
    #pragma unroll
    for (int i = 0; i < 4; i++) {
        const int r = rt4 + i;
        const float invd = 1.0f / den_s[256 + r];
        float v0, v1, v2, v3;
        unpack2(acc[i][0], v0, v1);
        unpack2(acc[i][1], v2, v3);
        v0 *= invd; v1 *= invd; v2 *= invd; v3 *= invd;
        v0 = (v0 > 0.0f) ? v0 : expm1f(v0);
        v1 = (v1 > 0.0f) ? v1 : expm1f(v1);
        v2 = (v2 > 0.0f) ? v2 : expm1f(v2);
        v3 = (v3 > 0.0f) ? v3 : expm1f(v3);
        *(float4*)(out + (size_t)(rbase + r) * FOUT + ct4) = make_float4(v0, v1, v2, v3);
    }
}

extern "C" void kernel_launch(void* const* d_in, const int* in_sizes, int n_in,
                              void* d_out, int out_size) {
    const float* x   = (const float*)d_in[0];   // [8192,128] f32
    const int*   adj = (const int*)  d_in[1];   // [8192,8192] i32
    const float* W   = (const float*)d_in[2];   // [128,64] f32
    const float* a   = (const float*)d_in[3];   // [128,1] f32
    float* out = (float*)d_out;                 // [8192,64] f32

    gat_proj<<<NN / 64, 256>>>(x, W, a);
    gat_attn<<<NN / RT, 256>>>(adj, out);
}

// round 12
// speedup vs baseline: 1.2861x; 1.2861x over previous
#include <cuda_runtime.h>
#include <cstdint>

#define NN   8192
#define FIN  128
#define FOUT 64
#define RT   64      // rows per CTA in attention kernel
#define JB   64      // j-chunk
#define HALF 4096    // j-range per CTA (split-K factor 2)
#define ALPHA_LR 0.2f

// Scratch (device globals — no allocation allowed)
__device__ __align__(16) float g_h[NN * FOUT];
__device__ __align__(16) float g_s1[NN];
__device__ __align__(16) float g_s2[NN];
__device__ __align__(16) float g_part[2][NN * FOUT];   // split-K partial numerators
__device__ __align__(16) float g_den[2][NN];           // split-K partial denominators

__device__ __forceinline__ unsigned long long pack2(float lo, float hi) {
    unsigned long long r;
    asm("mov.b64 %0, {%1, %2};" : "=l"(r) : "f"(lo), "f"(hi));
    return r;
}
__device__ __forceinline__ void unpack2(unsigned long long v, float& lo, float& hi) {
    asm("mov.b64 {%0, %1}, %2;" : "=f"(lo), "=f"(hi) : "l"(v));
}
// Packed fp32x2 FMA: d = a*b + d  (sm_100+; 2x FFMA throughput)
__device__ __forceinline__ void fma2(unsigned long long& d, unsigned long long a, unsigned long long b) {
    asm("fma.rn.f32x2 %0, %1, %2, %0;" : "+l"(d) : "l"(a), "l"(b));
}
__device__ __forceinline__ void cp16(unsigned int s, const void* g) {
    asm volatile("cp.async.cg.shared.global [%0], [%1], 16;" :: "r"(s), "l"(g));
}
__device__ __forceinline__ void cp_commit() {
    asm volatile("cp.async.commit_group;");
}
__device__ __forceinline__ void cp_wait0() {
    asm volatile("cp.async.wait_group 0;");
}

// ---------------------------------------------------------------------------
// Kernel 1: h = x @ W ; s1 = h @ a1 ; s2 = h @ a2
// 128 CTAs x 256 thr; thread = (row, 16-col group)
// ---------------------------------------------------------------------------
__global__ __launch_bounds__(256) void gat_proj(const float* __restrict__ x,
                                                const float* __restrict__ W,
                                                const float* __restrict__ a) {
    __shared__ float W_s[FIN][FOUT];   // 32 KB
    const int t = threadIdx.x;
    {
        const float4* Wg = (const float4*)W;
        float4* Ws = (float4*)&W_s[0][0];
        #pragma unroll
        for (int i = 0; i < 8; i++) Ws[t + 256 * i] = Wg[t + 256 * i];
    }
    __syncthreads();

    const int row = blockIdx.x * 64 + (t >> 2);
    const int cb  = (t & 3) * 16;

    float acc[16];
    #pragma unroll
    for (int c = 0; c < 16; c++) acc[c] = 0.0f;

    const float4* xr = (const float4*)(x + (size_t)row * FIN);
    #pragma unroll 8
    for (int k4 = 0; k4 < 32; k4++) {
        const float4 xv = xr[k4];
        const int k = k4 * 4;
        #pragma unroll
        for (int c = 0; c < 16; c++) {
            acc[c] = fmaf(xv.x, W_s[k    ][cb + c], acc[c]);
            acc[c] = fmaf(xv.y, W_s[k + 1][cb + c], acc[c]);
            acc[c] = fmaf(xv.z, W_s[k + 2][cb + c], acc[c]);
            acc[c] = fmaf(xv.w, W_s[k + 3][cb + c], acc[c]);
        }
    }

    float4* hw = (float4*)(g_h + (size_t)row * FOUT + cb);
    #pragma unroll
    for (int q = 0; q < 4; q++)
        hw[q] = make_float4(acc[q*4], acc[q*4+1], acc[q*4+2], acc[q*4+3]);

    float p1 = 0.0f, p2 = 0.0f;
    #pragma unroll
    for (int c = 0; c < 16; c++) {
        p1 = fmaf(acc[c], __ldg(&a[cb + c]),        p1);
        p2 = fmaf(acc[c], __ldg(&a[FOUT + cb + c]), p2);
    }
    p1 += __shfl_xor_sync(0xffffffffu, p1, 1);
    p1 += __shfl_xor_sync(0xffffffffu, p1, 2);
    p2 += __shfl_xor_sync(0xffffffffu, p2, 1);
    p2 += __shfl_xor_sync(0xffffffffu, p2, 2);
    if ((t & 3) == 0) { g_s1[row] = p1; g_s2[row] = p2; }
}

// ---------------------------------------------------------------------------
// Kernel 2: masked flash-attention numerator/denominator, split-K over j.
// 256 CTAs (= 128 row-blocks x 2 j-halves), 256 thr, 2 CTAs/SM.
// Per chunk of 64 j's:
//   cp.async h tile -> smem (issued at chunk top, hidden behind phase-1)
//   phase1: w = adj ? exp(lrelu(s1_i + s2_j)) : 0, stored as (w,w) pairs
//   phase2: 4x4 register microtile rank-1 updates with fma.rn.f32x2
// Partial results go to exclusive g_part[half]/g_den[half] slabs (no atomics).
// ---------------------------------------------------------------------------
__global__ __launch_bounds__(256, 2) void gat_attn(const int* __restrict__ adj) {
    __shared__ __align__(16) unsigned long long w2_s[JB][RT];  // 32 KB: (w,w) pairs, [j][row]
    __shared__ __align__(16) float h_s[JB][FOUT];              // 16 KB: [j][col]

    const int t = threadIdx.x;
    const int rbase = (blockIdx.x >> 1) * RT;
    const int half  = blockIdx.x & 1;
    const int joff  = half * HALF;

    // phase-1 identity: 4 threads per row, 16 j's each
    const int p1_row = t & 63;
    const int p1_js  = t >> 6;              // 0..3
    const float s1r  = g_s1[rbase + p1_row];
    float den = 0.0f;
    const int*   adj_row = adj + (size_t)(rbase + p1_row) * NN + joff + p1_js * 16;
    const float* s2b     = g_s2 + joff + p1_js * 16;

    // phase-2 identity: 16x16 thread grid, 4 rows x 4 cols microtile
    const int rt4 = (t >> 4) * 4;
    const int ct4 = (t & 15) * 4;

    unsigned long long acc[4][2];
    #pragma unroll
    for (int i = 0; i < 4; i++) { acc[i][0] = 0ull; acc[i][1] = 0ull; }

    const unsigned int hs_base =
        (unsigned int)__cvta_generic_to_shared(&h_s[0][0]) + t * 16;

    // register prefetch of adj + s2 for chunk 0
    int4   A0, A1, A2, A3;
    float4 S0, S1, S2, S3;
    {
        const int4* ap = (const int4*)adj_row;
        A0 = ap[0]; A1 = ap[1]; A2 = ap[2]; A3 = ap[3];
        const float4* sp = (const float4*)s2b;
        S0 = sp[0]; S1 = sp[1]; S2 = sp[2]; S3 = sp[3];
    }

    for (int jb = 0; jb < HALF; jb += JB) {
        __syncthreads();   // previous phase-2 done reading w2_s / h_s

        // async-copy this chunk's h tile (16 KB); completes during phase-1
        {
            const float* hsrc = g_h + (size_t)(joff + jb) * FOUT + t * 4;
            cp16(hs_base,         hsrc);
            cp16(hs_base + 4096,  hsrc + 1024);
            cp16(hs_base + 8192,  hsrc + 2048);
            cp16(hs_base + 12288, hsrc + 3072);
            cp_commit();
        }

        // phase-1: compute + store duplicated weights
        const int jl = p1_js * 16;
        #define WST(off, av, s2f) do {                          \
            float e = s1r + (s2f);                              \
            e = fmaxf(e, ALPHA_LR * e);       /* leaky relu */  \
            float w = ((av) > 0) ? __expf(e) : 0.0f;            \
            den += w;                                           \
            w2_s[jl + (off)][p1_row] = pack2(w, w);             \
        } while (0)
        WST(0,  A0.x, S0.x); WST(1,  A0.y, S0.y); WST(2,  A0.z, S0.z); WST(3,  A0.w, S0.w);
        WST(4,  A1.x, S1.x); WST(5,  A1.y, S1.y); WST(6,  A1.z, S1.z); WST(7,  A1.w, S1.w);
        WST(8,  A2.x, S2.x); WST(9,  A2.y, S2.y); WST(10, A2.z, S2.z); WST(11, A2.w, S2.w);
        WST(12, A3.x, S3.x); WST(13, A3.y, S3.y); WST(14, A3.z, S3.z); WST(15, A3.w, S3.w);
        #undef WST

        // prefetch next chunk's adj / s2 (hidden behind phase-2)
        const int jn = jb + JB;
        if (jn < HALF) {
            const int4* ap = (const int4*)(adj_row + jn);
            A0 = ap[0]; A1 = ap[1]; A2 = ap[2]; A3 = ap[3];
            const float4* sp = (const float4*)(s2b + jn);
            S0 = sp[0]; S1 = sp[1]; S2 = sp[2]; S3 = sp[3];
        }

        cp_wait0();
        __syncthreads();   // w2_s + h_s ready

        // phase-2: per j, 3 LDS.128 + 8 FFMA2
        #pragma unroll 8
        for (int jj = 0; jj < JB; jj++) {
            const ulonglong2 wa = *(const ulonglong2*)&w2_s[jj][rt4];
            const ulonglong2 wb = *(const ulonglong2*)&w2_s[jj][rt4 + 2];
            const ulonglong2 hv = *(const ulonglong2*)&h_s[jj][ct4];
            fma2(acc[0][0], wa.x, hv.x); fma2(acc[0][1], wa.x, hv.y);
            fma2(acc[1][0], wa.y, hv.x); fma2(acc[1][1], wa.y, hv.y);
            fma2(acc[2][0], wb.x, hv.x); fma2(acc[2][1], wb.x, hv.y);
            fma2(acc[3][0], wb.y, hv.x); fma2(acc[3][1], wb.y, hv.y);
        }
    }

    __syncthreads();
    // partial denominator reduction, overlaying h_s (phase-2 done)
    float* den_s = (float*)&h_s[0][0];
    den_s[p1_js * 64 + p1_row] = den;
    __syncthreads();
    if (t < 64) {
        g_den[half][rbase + t] =
            den_s[t] + den_s[64 + t] + den_s[128 + t] + den_s[192 + t];
    }

    // write partial numerators (exclusive slab, plain stores)
    float* pout = g_part[half];
    #pragma unroll
    for (int i = 0; i < 4; i++) {
        const int r = rt4 + i;
        float v0, v1, v2, v3;
        unpack2(acc[i][0], v0, v1);
        unpack2(acc[i][1], v2, v3);
        *(float4*)(pout + (size_t)(rbase + r) * FOUT + ct4) = make_float4(v0, v1, v2, v3);
    }
}

// ---------------------------------------------------------------------------
// Kernel 3: combine split-K halves, normalize, ELU, store.
// 512 CTAs x 256 thr; one float4 per thread.
// ---------------------------------------------------------------------------
__global__ __launch_bounds__(256) void gat_finish(float* __restrict__ out) {
    const int idx = blockIdx.x * 256 + threadIdx.x;   // float4 index, 131072 total
    const int row = idx >> 4;                         // 16 float4 per row
    const float invd = 1.0f / (g_den[0][row] + g_den[1][row]);
    const float4 p0 = ((const float4*)g_part[0])[idx];
    const float4 p1 = ((const float4*)g_part[1])[idx];
    float v0 = (p0.x + p1.x) * invd;
    float v1 = (p0.y + p1.y) * invd;
    float v2 = (p0.z + p1.z) * invd;
    float v3 = (p0.w + p1.w) * invd;
    v0 = (v0 > 0.0f) ? v0 : expm1f(v0);
    v1 = (v1 > 0.0f) ? v1 : expm1f(v1);
    v2 = (v2 > 0.0f) ? v2 : expm1f(v2);
    v3 = (v3 > 0.0f) ? v3 : expm1f(v3);
    ((float4*)out)[idx] = make_float4(v0, v1, v2, v3);
}

extern "C" void kernel_launch(void* const* d_in, const int* in_sizes, int n_in,
                              void* d_out, int out_size) {
    const float* x   = (const float*)d_in[0];   // [8192,128] f32
    const int*   adj = (const int*)  d_in[1];   // [8192,8192] i32
    const float* W   = (const float*)d_in[2];   // [128,64] f32
    const float* a   = (const float*)d_in[3];   // [128,1] f32
    float* out = (float*)d_out;                 // [8192,64] f32

    gat_proj<<<NN / 64, 256>>>(x, W, a);
    gat_attn<<<(NN / RT) * 2, 256>>>(adj);
    gat_finish<<<NN * FOUT / 4 / 256, 256>>>(out);
}

// round 13
// speedup vs baseline: 1.2865x; 1.0004x over previous
#include <cuda_runtime.h>
#include <cstdint>

#define NN   8192
#define FIN  128
#define FOUT 64
#define RT   64      // rows per CTA in attention kernel
#define JB   64      // j-chunk
#define HALF 4096    // j-range per CTA (split-K factor 2)
#define ALPHA_LR 0.2f

// Scratch (device globals — no allocation allowed)
__device__ __align__(16) float g_h[NN * FOUT];
__device__ __align__(16) float g_s1[NN];
__device__ __align__(16) float g_s2[NN];
__device__ __align__(16) float g_part[2][NN * FOUT];   // split-K partial numerators
__device__ __align__(16) float g_den[2][NN];           // split-K partial denominators

__device__ __forceinline__ unsigned long long pack2(float lo, float hi) {
    unsigned long long r;
    asm("mov.b64 %0, {%1, %2};" : "=l"(r) : "f"(lo), "f"(hi));
    return r;
}
__device__ __forceinline__ void unpack2(unsigned long long v, float& lo, float& hi) {
    asm("mov.b64 {%0, %1}, %2;" : "=f"(lo), "=f"(hi) : "l"(v));
}
// Packed fp32x2 FMA: d = a*b + d  (sm_100+; 2x FFMA throughput)
__device__ __forceinline__ void fma2(unsigned long long& d, unsigned long long a, unsigned long long b) {
    asm("fma.rn.f32x2 %0, %1, %2, %0;" : "+l"(d) : "l"(a), "l"(b));
}
__device__ __forceinline__ void cp16(unsigned int s, const void* g) {
    asm volatile("cp.async.cg.shared.global [%0], [%1], 16;" :: "r"(s), "l"(g));
}
__device__ __forceinline__ void cp_commit() {
    asm volatile("cp.async.commit_group;");
}
__device__ __forceinline__ void cp_wait0() {
    asm volatile("cp.async.wait_group 0;");
}

// ---------------------------------------------------------------------------
// Kernel 1: h = x @ W ; s1 = h @ a1 ; s2 = h @ a2
// 128 CTAs x 256 thr; thread = (row, 16-col group)
// ---------------------------------------------------------------------------
__global__ __launch_bounds__(256) void gat_proj(const float* __restrict__ x,
                                                const float* __restrict__ W,
                                                const float* __restrict__ a) {
    __shared__ float W_s[FIN][FOUT];   // 32 KB
    const int t = threadIdx.x;
    {
        const float4* Wg = (const float4*)W;
        float4* Ws = (float4*)&W_s[0][0];
        #pragma unroll
        for (int i = 0; i < 8; i++) Ws[t + 256 * i] = Wg[t + 256 * i];
    }
    __syncthreads();

    const int row = blockIdx.x * 64 + (t >> 2);
    const int cb  = (t & 3) * 16;

    float acc[16];
    #pragma unroll
    for (int c = 0; c < 16; c++) acc[c] = 0.0f;

    const float4* xr = (const float4*)(x + (size_t)row * FIN);
    #pragma unroll 8
    for (int k4 = 0; k4 < 32; k4++) {
        const float4 xv = xr[k4];
        const int k = k4 * 4;
        #pragma unroll
        for (int c = 0; c < 16; c++) {
            acc[c] = fmaf(xv.x, W_s[k    ][cb + c], acc[c]);
            acc[c] = fmaf(xv.y, W_s[k + 1][cb + c], acc[c]);
            acc[c] = fmaf(xv.z, W_s[k + 2][cb + c], acc[c]);
            acc[c] = fmaf(xv.w, W_s[k + 3][cb + c], acc[c]);
        }
    }

    float4* hw = (float4*)(g_h + (size_t)row * FOUT + cb);
    #pragma unroll
    for (int q = 0; q < 4; q++)
        hw[q] = make_float4(acc[q*4], acc[q*4+1], acc[q*4+2], acc[q*4+3]);

    float p1 = 0.0f, p2 = 0.0f;
    #pragma unroll
    for (int c = 0; c < 16; c++) {
        p1 = fmaf(acc[c], __ldg(&a[cb + c]),        p1);
        p2 = fmaf(acc[c], __ldg(&a[FOUT + cb + c]), p2);
    }
    p1 += __shfl_xor_sync(0xffffffffu, p1, 1);
    p1 += __shfl_xor_sync(0xffffffffu, p1, 2);
    p2 += __shfl_xor_sync(0xffffffffu, p2, 1);
    p2 += __shfl_xor_sync(0xffffffffu, p2, 2);
    if ((t & 3) == 0) { g_s1[row] = p1; g_s2[row] = p2; }
}

// ---------------------------------------------------------------------------
// Kernel 2: masked flash-attention numerator/denominator, split-K over j.
// 256 CTAs (= 128 row-blocks x 2 j-halves), 256 thr, 2 CTAs/SM.
// Per chunk of 64 j's:
//   cp.async h tile -> smem (issued at chunk top, hidden behind phase-1)
//   phase1: w = adj ? exp(lrelu(s1_i + s2_j)) : 0, stored as (w,w) pairs
//   phase2: 4x4 register microtile rank-1 updates with fma.rn.f32x2
// Partial results go to exclusive g_part[half]/g_den[half] slabs (no atomics).
// ---------------------------------------------------------------------------
__global__ __launch_bounds__(256, 2) void gat_attn(const int* __restrict__ adj) {
    __shared__ __align__(16) unsigned long long w2_s[JB][RT];  // 32 KB: (w,w) pairs, [j][row]
    __shared__ __align__(16) float h_s[JB][FOUT];              // 16 KB: [j][col]

    const int t = threadIdx.x;
    const int rbase = (blockIdx.x >> 1) * RT;
    const int half  = blockIdx.x & 1;
    const int joff  = half * HALF;

    // phase-1 identity: 4 threads per row, 16 j's each
    const int p1_row = t & 63;
    const int p1_js  = t >> 6;              // 0..3
    const float s1r  = g_s1[rbase + p1_row];
    float den = 0.0f;
    const int*   adj_row = adj + (size_t)(rbase + p1_row) * NN + joff + p1_js * 16;
    const float* s2b     = g_s2 + joff + p1_js * 16;

    // phase-2 identity: 16x16 thread grid, 4 rows x 4 cols microtile
    const int rt4 = (t >> 4) * 4;
    const int ct4 = (t & 15) * 4;

    unsigned long long acc[4][2];
    #pragma unroll
    for (int i = 0; i < 4; i++) { acc[i][0] = 0ull; acc[i][1] = 0ull; }

    const unsigned int hs_base =
        (unsigned int)__cvta_generic_to_shared(&h_s[0][0]) + t * 16;

    // register prefetch of adj + s2 for chunk 0
    int4   A0, A1, A2, A3;
    float4 S0, S1, S2, S3;
    {
        const int4* ap = (const int4*)adj_row;
        A0 = ap[0]; A1 = ap[1]; A2 = ap[2]; A3 = ap[3];
        const float4* sp = (const float4*)s2b;
        S0 = sp[0]; S1 = sp[1]; S2 = sp[2]; S3 = sp[3];
    }

    for (int jb = 0; jb < HALF; jb += JB) {
        __syncthreads();   // previous phase-2 done reading w2_s / h_s

        // async-copy this chunk's h tile (16 KB); completes during phase-1
        {
            const float* hsrc = g_h + (size_t)(joff + jb) * FOUT + t * 4;
            cp16(hs_base,         hsrc);
            cp16(hs_base + 4096,  hsrc + 1024);
            cp16(hs_base + 8192,  hsrc + 2048);
            cp16(hs_base + 12288, hsrc + 3072);
            cp_commit();
        }

        // phase-1: compute + store duplicated weights
        const int jl = p1_js * 16;
        #define WST(off, av, s2f) do {                          \
            float e = s1r + (s2f);                              \
            e = fmaxf(e, ALPHA_LR * e);       /* leaky relu */  \
            float w = ((av) > 0) ? __expf(e) : 0.0f;            \
            den += w;                                           \
            w2_s[jl + (off)][p1_row] = pack2(w, w);             \
        } while (0)
        WST(0,  A0.x, S0.x); WST(1,  A0.y, S0.y); WST(2,  A0.z, S0.z); WST(3,  A0.w, S0.w);
        WST(4,  A1.x, S1.x); WST(5,  A1.y, S1.y); WST(6,  A1.z, S1.z); WST(7,  A1.w, S1.w);
        WST(8,  A2.x, S2.x); WST(9,  A2.y, S2.y); WST(10, A2.z, S2.z); WST(11, A2.w, S2.w);
        WST(12, A3.x, S3.x); WST(13, A3.y, S3.y); WST(14, A3.z, S3.z); WST(15, A3.w, S3.w);
        #undef WST

        // prefetch next chunk's adj / s2 (hidden behind phase-2)
        const int jn = jb + JB;
        if (jn < HALF) {
            const int4* ap = (const int4*)(adj_row + jn);
            A0 = ap[0]; A1 = ap[1]; A2 = ap[2]; A3 = ap[3];
            const float4* sp = (const float4*)(s2b + jn);
            S0 = sp[0]; S1 = sp[1]; S2 = sp[2]; S3 = sp[3];
        }

        cp_wait0();
        __syncthreads();   // w2_s + h_s ready

        // phase-2: per j, 3 LDS.128 + 8 FFMA2
        #pragma unroll 8
        for (int jj = 0; jj < JB; jj++) {
            const ulonglong2 wa = *(const ulonglong2*)&w2_s[jj][rt4];
            const ulonglong2 wb = *(const ulonglong2*)&w2_s[jj][rt4 + 2];
            const ulonglong2 hv = *(const ulonglong2*)&h_s[jj][ct4];
            fma2(acc[0][0], wa.x, hv.x); fma2(acc[0][1], wa.x, hv.y);
            fma2(acc[1][0], wa.y, hv.x); fma2(acc[1][1], wa.y, hv.y);
            fma2(acc[2][0], wb.x, hv.x); fma2(acc[2][1], wb.x, hv.y);
            fma2(acc[3][0], wb.y, hv.x); fma2(acc[3][1], wb.y, hv.y);
        }
    }

    __syncthreads();
    // partial denominator reduction, overlaying h_s (phase-2 done)
    float* den_s = (float*)&h_s[0][0];
    den_s[p1_js * 64 + p1_row] = den;
    __syncthreads();
    if (t < 64) {
        g_den[half][rbase + t] =
            den_s[t] + den_s[64 + t] + den_s[128 + t] + den_s[192 + t];
    }

    // write partial numerators (exclusive slab, plain stores)
    float* pout = g_part[half];
    #pragma unroll
    for (int i = 0; i < 4; i++) {
        const int r = rt4 + i;
        float v0, v1, v2, v3;
        unpack2(acc[i][0], v0, v1);
        unpack2(acc[i][1], v2, v3);
        *(float4*)(pout + (size_t)(rbase + r) * FOUT + ct4) = make_float4(v0, v1, v2, v3);
    }
}

// ---------------------------------------------------------------------------
// Kernel 3: combine split-K halves, normalize, ELU, store.
// 512 CTAs x 256 thr; one float4 per thread.
// ---------------------------------------------------------------------------
__global__ __launch_bounds__(256) void gat_finish(float* __restrict__ out) {
    const int idx = blockIdx.x * 256 + threadIdx.x;   // float4 index, 131072 total
    const int row = idx >> 4;                         // 16 float4 per row
    const float invd = 1.0f / (g_den[0][row] + g_den[1][row]);
    const float4 p0 = ((const float4*)g_part[0])[idx];
    const float4 p1 = ((const float4*)g_part[1])[idx];
    float v0 = (p0.x + p1.x) * invd;
    float v1 = (p0.y + p1.y) * invd;
    float v2 = (p0.z + p1.z) * invd;
    float v3 = (p0.w + p1.w) * invd;
    v0 = (v0 > 0.0f) ? v0 : expm1f(v0);
    v1 = (v1 > 0.0f) ? v1 : expm1f(v1);
    v2 = (v2 > 0.0f) ? v2 : expm1f(v2);
    v3 = (v3 > 0.0f) ? v3 : expm1f(v3);
    ((float4*)out)[idx] = make_float4(v0, v1, v2, v3);
}

extern "C" void kernel_launch(void* const* d_in, const int* in_sizes, int n_in,
                              void* d_out, int out_size) {
    const float* x   = (const float*)d_in[0];   // [8192,128] f32
    const int*   adj = (const int*)  d_in[1];   // [8192,8192] i32
    const float* W   = (const float*)d_in[2];   // [128,64] f32
    const float* a   = (const float*)d_in[3];   // [128,1] f32
    float* out = (float*)d_out;                 // [8192,64] f32

    gat_proj<<<NN / 64, 256>>>(x, W, a);
    gat_attn<<<(NN / RT) * 2, 256>>>(adj);
    gat_finish<<<NN * FOUT / 4 / 256, 256>>>(out);
}